// round 1
// baseline (speedup 1.0000x reference)
#include <cuda_runtime.h>
#include <cstdint>

// ROI Align, P=7, S=2, SCALE=0.125
// x: (8, 256, 100, 100) fp32   rois: (512, 5) fp32
// out: (512, 256, 7, 7) fp32
//
// One thread per output element. Warp covers consecutive bins of one
// (roi, channel) -> gathers land in a single ~28x28 patch (L1-friendly),
// output writes fully coalesced.

#define NIMG 8
#define C_   256
#define H_   100
#define W_   100
#define R_   512
#define P_   7
#define HW_  (H_ * W_)

__device__ __forceinline__ void axis_terms(float c, int L,
                                           int& lo, int& hi,
                                           float& wlo, float& whi) {
    bool valid = (c > -1.0f) && (c < (float)L);
    float cc = fminf(fmaxf(c, 0.0f), (float)(L - 1));
    int l = (int)floorf(cc);
    if (l > L - 1) l = L - 1;
    int h = min(l + 1, L - 1);
    float frac = cc - (float)l;
    lo = l;
    hi = h;
    wlo = valid ? (1.0f - frac) : 0.0f;
    whi = valid ? frac : 0.0f;
}

__global__ void __launch_bounds__(256)
roi_align_kernel(const float* __restrict__ x,
                 const float* __restrict__ rois,
                 float* __restrict__ out,
                 int total) {
    int o = blockIdx.x * blockDim.x + threadIdx.x;
    if (o >= total) return;

    // Decompose o = ((r*C + c)*P + ph)*P + pw
    int pw = o % P_;
    int t  = o / P_;
    int ph = t % P_;
    t /= P_;
    int c = t % C_;
    int r = t / C_;

    const float* roi = rois + (size_t)r * 5;
    float r0 = __ldg(roi + 0);
    float r1 = __ldg(roi + 1);
    float r2 = __ldg(roi + 2);
    float r3 = __ldg(roi + 3);
    float r4 = __ldg(roi + 4);

    int b = (int)r0;
    float sx = r1 * 0.125f - 0.5f;
    float sy = r2 * 0.125f - 0.5f;
    float bw = (r3 * 0.125f - 0.5f - sx) * (1.0f / 7.0f);
    float bh = (r4 * 0.125f - 0.5f - sy) * (1.0f / 7.0f);

    const float* px = x + ((size_t)b * C_ + c) * HW_;

    int   yl[2], yh[2], xl[2], xh[2];
    float wy1[2], wy2[2], wx1[2], wx2[2];

#pragma unroll
    for (int s = 0; s < 2; s++) {
        float frac = s ? 0.75f : 0.25f;
        float gy = (float)ph + frac;
        float gx = (float)pw + frac;
        axis_terms(fmaf(gy, bh, sy), H_, yl[s], yh[s], wy1[s], wy2[s]);
        axis_terms(fmaf(gx, bw, sx), W_, xl[s], xh[s], wx1[s], wx2[s]);
    }

    float acc = 0.0f;
#pragma unroll
    for (int i = 0; i < 2; i++) {
        const float* rowl = px + yl[i] * W_;
        const float* rowh = px + yh[i] * W_;
#pragma unroll
        for (int j = 0; j < 2; j++) {
            float vll = __ldg(rowl + xl[j]);
            float vlh = __ldg(rowl + xh[j]);
            float vhl = __ldg(rowh + xl[j]);
            float vhh = __ldg(rowh + xh[j]);
            acc += wy1[i] * (wx1[j] * vll + wx2[j] * vlh)
                 + wy2[i] * (wx1[j] * vhl + wx2[j] * vhh);
        }
    }

    out[o] = acc * 0.25f;
}

extern "C" void kernel_launch(void* const* d_in, const int* in_sizes, int n_in,
                              void* d_out, int out_size) {
    const float* x    = (const float*)d_in[0];
    const float* rois = (const float*)d_in[1];
    float* out = (float*)d_out;

    int total = out_size;  // 512*256*7*7 = 6,422,528
    int threads = 256;
    int blocks = (total + threads - 1) / threads;
    roi_align_kernel<<<blocks, threads>>>(x, rois, out, total);
}